// round 2
// baseline (speedup 1.0000x reference)
#include <cuda_runtime.h>
#include <stdint.h>

#define N_NODES 10000
#define N_EDGES 320000
#define N_PAIRS 2048
#define IN_CH   128
#define HIDDEN  512
#define ROW_U4  (N_NODES / 16)   // 625 uint4 chunks per adjacency row

// 100 MB uint8 adjacency count matrix (zero-initialized at module load;
// each launch self-cleans the cells it touched, so replays start from zero).
__device__ __align__(16) unsigned char g_A[(size_t)N_NODES * N_NODES];
// xs features: [N_PAIRS][2*IN_CH]  (first 128 = x_i*x_j, next 128 = cn_emb)
__device__ __align__(16) float g_XS[N_PAIRS * 2 * IN_CH];
// 1 if index buffers are int64, 0 if int32 (set by detect_kernel each launch)
__device__ int g_is64;

// ---------------------------------------------------------------------------
// 0) Detect index dtype: int64 values < 2^32 have all-zero odd 32-bit words.
// ---------------------------------------------------------------------------
__global__ void detect_kernel(const unsigned int* __restrict__ ei32) {
    bool all0 = true;
    for (int j = threadIdx.x; j < 256; j += 32)
        if (ei32[2 * j + 1] != 0u) all0 = false;
    unsigned m = __ballot_sync(0xFFFFFFFFu, all0);
    if (threadIdx.x == 0) g_is64 = (m == 0xFFFFFFFFu) ? 1 : 0;
}

__device__ __forceinline__ long long load_idx(const void* p, long long j) {
    if (g_is64) return ((const long long*)p)[j];
    return (long long)((const int*)p)[j];
}

// ---------------------------------------------------------------------------
// 1) Scatter: A[s][d] += 1, A[d][s] += 1 for every edge (byte-packed atomics)
// ---------------------------------------------------------------------------
__global__ void scatter_kernel(const void* __restrict__ ei) {
    int e = blockIdx.x * blockDim.x + threadIdx.x;
    if (e >= N_EDGES) return;
    long long s = load_idx(ei, e);
    long long d = load_idx(ei, (long long)N_EDGES + e);
    unsigned int* A32 = reinterpret_cast<unsigned int*>(g_A);
    size_t i1 = (size_t)s * N_NODES + (size_t)d;
    size_t i2 = (size_t)d * N_NODES + (size_t)s;
    atomicAdd(&A32[i1 >> 2], 1u << ((i1 & 3) * 8));
    atomicAdd(&A32[i2 >> 2], 1u << ((i2 & 3) * 8));
}

// ---------------------------------------------------------------------------
// 4) Clear only the touched cells (runs after pairs_kernel read A)
// ---------------------------------------------------------------------------
__global__ void clear_kernel(const void* __restrict__ ei) {
    int e = blockIdx.x * blockDim.x + threadIdx.x;
    if (e >= N_EDGES) return;
    long long s = load_idx(ei, e);
    long long d = load_idx(ei, (long long)N_EDGES + e);
    g_A[(size_t)s * N_NODES + (size_t)d] = 0;
    g_A[(size_t)d * N_NODES + (size_t)s] = 0;
}

// ---------------------------------------------------------------------------
// 2) Per-pair: intersect rows A[ti], A[tj]; build xs[b] = [x_i*x_j, cn_emb]
//    One block (128 threads) per pair.
// ---------------------------------------------------------------------------
__global__ void pairs_kernel(const void* __restrict__ tar,
                             const float* __restrict__ x) {
    __shared__ int   s_n[512];
    __shared__ float s_w[512];
    __shared__ int   s_cnt;

    int b   = blockIdx.x;
    int tid = threadIdx.x;   // 0..127
    if (tid == 0) s_cnt = 0;
    __syncthreads();

    long long ti = load_idx(tar, b);
    long long tj = load_idx(tar, (long long)N_PAIRS + b);

    const uint4* rowi = reinterpret_cast<const uint4*>(g_A + (size_t)ti * N_NODES);
    const uint4* rowj = reinterpret_cast<const uint4*>(g_A + (size_t)tj * N_NODES);

    for (int c = tid; c < ROW_U4; c += 128) {
        uint4 a = rowi[c];
        uint4 q = rowj[c];
        unsigned int aw[4] = {a.x, a.y, a.z, a.w};
        unsigned int bw[4] = {q.x, q.y, q.z, q.w};
#pragma unroll
        for (int w = 0; w < 4; w++) {
            unsigned int av = aw[w], bv = bw[w];
            if (av == 0u || bv == 0u) continue;
#pragma unroll
            for (int k = 0; k < 4; k++) {
                unsigned int ua = (av >> (8 * k)) & 0xFFu;
                unsigned int ub = (bv >> (8 * k)) & 0xFFu;
                if (ua && ub) {
                    int idx = atomicAdd(&s_cnt, 1);
                    if (idx < 512) {
                        s_n[idx] = c * 16 + w * 4 + k;
                        s_w[idx] = (float)(ua * ub);
                    }
                }
            }
        }
    }
    __syncthreads();

    int cnt = s_cnt < 512 ? s_cnt : 512;

    // channel tid for this pair
    float xi = x[(size_t)ti * IN_CH + tid];
    float xj = x[(size_t)tj * IN_CH + tid];

    float acc = 0.f;
    for (int e = 0; e < cnt; e++) {
        acc = fmaf(s_w[e], x[(size_t)s_n[e] * IN_CH + tid], acc);
    }

    g_XS[(size_t)b * (2 * IN_CH) + tid]          = xi * xj;
    g_XS[(size_t)b * (2 * IN_CH) + IN_CH + tid]  = acc;
}

// ---------------------------------------------------------------------------
// 3) Fused MLP: out[b] = sum_h relu(xs[b,:] . W1[:,h] + b1[h]) * W2[h] + b2
//    PB=16 pairs per block, 512 threads (one hidden unit each).
// ---------------------------------------------------------------------------
#define PB 16

__global__ __launch_bounds__(HIDDEN, 1)
void mlp_kernel(const float* __restrict__ W1, const float* __restrict__ b1,
                const float* __restrict__ W2, const float* __restrict__ b2,
                float* __restrict__ out) {
    __shared__ float s_xs[PB][2 * IN_CH];   // 16 KB
    __shared__ float s_red[16][PB];         // [warp][pair]

    int h  = threadIdx.x;       // 0..511
    int b0 = blockIdx.x * PB;

    // cooperative load of xs tile (coalesced)
    const float* xs_src = &g_XS[(size_t)b0 * (2 * IN_CH)];
    for (int i = threadIdx.x; i < PB * 2 * IN_CH; i += HIDDEN)
        (&s_xs[0][0])[i] = xs_src[i];
    __syncthreads();

    float acc[PB];
#pragma unroll
    for (int p = 0; p < PB; p++) acc[p] = 0.f;

    for (int k = 0; k < 2 * IN_CH; k += 4) {
        float w0 = W1[(size_t)(k + 0) * HIDDEN + h];
        float w1 = W1[(size_t)(k + 1) * HIDDEN + h];
        float w2 = W1[(size_t)(k + 2) * HIDDEN + h];
        float w3 = W1[(size_t)(k + 3) * HIDDEN + h];
#pragma unroll
        for (int p = 0; p < PB; p++) {
            float4 xv = *reinterpret_cast<const float4*>(&s_xs[p][k]);
            float a = acc[p];
            a = fmaf(xv.x, w0, a);
            a = fmaf(xv.y, w1, a);
            a = fmaf(xv.z, w2, a);
            a = fmaf(xv.w, w3, a);
            acc[p] = a;
        }
    }

    float bh  = b1[h];
    float w2h = W2[h];
    float vals[PB];
#pragma unroll
    for (int p = 0; p < PB; p++)
        vals[p] = fmaxf(acc[p] + bh, 0.f) * w2h;

    // reduce over the 512 hidden threads per pair
#pragma unroll
    for (int p = 0; p < PB; p++) {
#pragma unroll
        for (int off = 16; off > 0; off >>= 1)
            vals[p] += __shfl_down_sync(0xFFFFFFFFu, vals[p], off);
    }
    int warp = threadIdx.x >> 5;
    int lane = threadIdx.x & 31;
    if (lane == 0) {
#pragma unroll
        for (int p = 0; p < PB; p++) s_red[warp][p] = vals[p];
    }
    __syncthreads();

    if (threadIdx.x < PB) {
        float s = 0.f;
#pragma unroll
        for (int w = 0; w < 16; w++) s += s_red[w][threadIdx.x];
        out[b0 + threadIdx.x] = s + b2[0];
    }
}

// ---------------------------------------------------------------------------
// launch
// ---------------------------------------------------------------------------
extern "C" void kernel_launch(void* const* d_in, const int* in_sizes, int n_in,
                              void* d_out, int out_size) {
    const float* x   = (const float*)d_in[0];
    const void*  ei  = d_in[1];
    const void*  tar = d_in[2];
    const float* W1  = (const float*)d_in[3];
    const float* b1  = (const float*)d_in[4];
    const float* W2  = (const float*)d_in[5];
    const float* b2  = (const float*)d_in[6];
    float*       out = (float*)d_out;

    (void)in_sizes; (void)n_in; (void)out_size;

    detect_kernel<<<1, 32>>>((const unsigned int*)ei);
    scatter_kernel<<<(N_EDGES + 255) / 256, 256>>>(ei);
    pairs_kernel<<<N_PAIRS, 128>>>(tar, x);
    clear_kernel<<<(N_EDGES + 255) / 256, 256>>>(ei);
    mlp_kernel<<<N_PAIRS / PB, HIDDEN>>>(W1, b1, W2, b2, out);
}

// round 3
// speedup vs baseline: 1.2284x; 1.2284x over previous
#include <cuda_runtime.h>
#include <stdint.h>

#define N_NODES 10000
#define N_EDGES 320000
#define N_PAIRS 2048
#define IN_CH   128
#define HIDDEN  512

// 4-bit counts, row stride 5120 bytes (1280 u32 words, 16B aligned, covers
// 10240 nibble columns >= 10000). Total 51.2 MB -> fully L2 resident.
#define ROW_W   1280
#define ROW_U4  320              // uint4 chunks per row (32 nibbles each)

__device__ __align__(16) unsigned int g_A[(size_t)N_NODES * ROW_W];
// xs features: [N_PAIRS][2*IN_CH]  (first 128 = x_i*x_j, next 128 = cn_emb)
__device__ __align__(16) float g_XS[N_PAIRS * 2 * IN_CH];
// 1 if index buffers are int64, 0 if int32 (set by detect_kernel each launch)
__device__ int g_is64;

// ---------------------------------------------------------------------------
// 0) Detect index dtype: int64 values < 2^32 have all-zero odd 32-bit words.
// ---------------------------------------------------------------------------
__global__ void detect_kernel(const unsigned int* __restrict__ ei32) {
    bool all0 = true;
    for (int j = threadIdx.x; j < 256; j += 32)
        if (ei32[2 * j + 1] != 0u) all0 = false;
    unsigned m = __ballot_sync(0xFFFFFFFFu, all0);
    if (threadIdx.x == 0) g_is64 = (m == 0xFFFFFFFFu) ? 1 : 0;
}

__device__ __forceinline__ long long load_idx(const void* p, long long j) {
    if (g_is64) return ((const long long*)p)[j];
    return (long long)((const int*)p)[j];
}

// ---------------------------------------------------------------------------
// 1) Scatter: nibble(A[s][d]) += 1, nibble(A[d][s]) += 1 (L2-resident atomics)
// ---------------------------------------------------------------------------
__global__ void scatter_kernel(const void* __restrict__ ei) {
    int e = blockIdx.x * blockDim.x + threadIdx.x;
    if (e >= N_EDGES) return;
    long long s = load_idx(ei, e);
    long long d = load_idx(ei, (long long)N_EDGES + e);
    size_t w1 = (size_t)s * ROW_W + (size_t)(d >> 3);
    size_t w2 = (size_t)d * ROW_W + (size_t)(s >> 3);
    atomicAdd(&g_A[w1], 1u << ((d & 7) * 4));
    atomicAdd(&g_A[w2], 1u << ((s & 7) * 4));
}

// ---------------------------------------------------------------------------
// 4) Clear only the touched nibbles (restores zeros for next graph replay)
// ---------------------------------------------------------------------------
__global__ void clear_kernel(const void* __restrict__ ei) {
    int e = blockIdx.x * blockDim.x + threadIdx.x;
    if (e >= N_EDGES) return;
    long long s = load_idx(ei, e);
    long long d = load_idx(ei, (long long)N_EDGES + e);
    size_t w1 = (size_t)s * ROW_W + (size_t)(d >> 3);
    size_t w2 = (size_t)d * ROW_W + (size_t)(s >> 3);
    atomicAnd(&g_A[w1], ~(0xFu << ((d & 7) * 4)));
    atomicAnd(&g_A[w2], ~(0xFu << ((s & 7) * 4)));
}

// ---------------------------------------------------------------------------
// 2) Per-pair: intersect nibble rows A[ti], A[tj]; build xs[b]
//    One block (128 threads) per pair.
// ---------------------------------------------------------------------------
__device__ __forceinline__ unsigned nzmask(unsigned v) {
    // bit 4j set iff nibble j of v is nonzero
    return (v | (v >> 1) | (v >> 2) | (v >> 3)) & 0x11111111u;
}

__global__ void pairs_kernel(const void* __restrict__ tar,
                             const float* __restrict__ x) {
    __shared__ int   s_n[512];
    __shared__ float s_w[512];
    __shared__ int   s_cnt;

    int b   = blockIdx.x;
    int tid = threadIdx.x;   // 0..127
    if (tid == 0) s_cnt = 0;
    __syncthreads();

    long long ti = load_idx(tar, b);
    long long tj = load_idx(tar, (long long)N_PAIRS + b);

    const uint4* rowi = reinterpret_cast<const uint4*>(&g_A[(size_t)ti * ROW_W]);
    const uint4* rowj = reinterpret_cast<const uint4*>(&g_A[(size_t)tj * ROW_W]);

    for (int c = tid; c < ROW_U4; c += 128) {
        uint4 a = rowi[c];
        uint4 q = rowj[c];
        unsigned int aw[4] = {a.x, a.y, a.z, a.w};
        unsigned int bw[4] = {q.x, q.y, q.z, q.w};
#pragma unroll
        for (int w = 0; w < 4; w++) {
            unsigned int av = aw[w], bv = bw[w];
            unsigned int m = nzmask(av) & nzmask(bv);
            while (m) {
                int bit = __ffs(m) - 1;           // 4*nibble
                unsigned ua = (av >> bit) & 0xFu;
                unsigned ub = (bv >> bit) & 0xFu;
                int idx = atomicAdd(&s_cnt, 1);
                if (idx < 512) {
                    s_n[idx] = c * 32 + w * 8 + (bit >> 2);
                    s_w[idx] = (float)(ua * ub);
                }
                m &= m - 1;
            }
        }
    }
    __syncthreads();

    int cnt = s_cnt < 512 ? s_cnt : 512;

    float xi = x[(size_t)ti * IN_CH + tid];
    float xj = x[(size_t)tj * IN_CH + tid];

    float acc = 0.f;
    for (int e = 0; e < cnt; e++)
        acc = fmaf(s_w[e], x[(size_t)s_n[e] * IN_CH + tid], acc);

    g_XS[(size_t)b * (2 * IN_CH) + tid]         = xi * xj;
    g_XS[(size_t)b * (2 * IN_CH) + IN_CH + tid] = acc;
}

// ---------------------------------------------------------------------------
// 3) Fused MLP with packed f32x2 FMA.
//    PB=16 pairs per block, 512 threads (one hidden unit each).
//    xs tile transposed in SMEM: s_xs[k][pair] so pair-dim is contiguous.
// ---------------------------------------------------------------------------
#define PB 16
#define XS_PAD 20   // floats per k-row (16 used); k*20*4 bytes keeps 16B align

__device__ __forceinline__ unsigned long long fma2(
    unsigned long long a, unsigned long long b, unsigned long long c) {
    unsigned long long d;
    asm("fma.rn.f32x2 %0, %1, %2, %3;" : "=l"(d) : "l"(a), "l"(b), "l"(c));
    return d;
}

__global__ __launch_bounds__(HIDDEN, 1)
void mlp_kernel(const float* __restrict__ W1, const float* __restrict__ b1,
                const float* __restrict__ W2, const float* __restrict__ b2,
                float* __restrict__ out) {
    __shared__ __align__(16) float s_xs[2 * IN_CH][XS_PAD];  // 20 KB
    __shared__ float s_red[16][PB];

    int h  = threadIdx.x;       // 0..511
    int b0 = blockIdx.x * PB;

    // cooperative transposed load of xs tile
    const float* xs_src = &g_XS[(size_t)b0 * (2 * IN_CH)];
    for (int i = threadIdx.x; i < PB * 2 * IN_CH; i += HIDDEN) {
        int p = i >> 8;           // i / 256
        int k = i & 255;
        s_xs[k][p] = xs_src[i];
    }
    __syncthreads();

    unsigned long long acc2[PB / 2];
#pragma unroll
    for (int q = 0; q < PB / 2; q++) acc2[q] = 0ull;

    for (int k = 0; k < 2 * IN_CH; k++) {
        float w = W1[(size_t)k * HIDDEN + h];
        unsigned long long ww;
        asm("mov.b64 %0, {%1, %1};" : "=l"(ww) : "r"(__float_as_uint(w)));
#pragma unroll
        for (int q4 = 0; q4 < PB / 4; q4++) {
            ulonglong2 xv = *reinterpret_cast<const ulonglong2*>(&s_xs[k][4 * q4]);
            acc2[2 * q4 + 0] = fma2(xv.x, ww, acc2[2 * q4 + 0]);
            acc2[2 * q4 + 1] = fma2(xv.y, ww, acc2[2 * q4 + 1]);
        }
    }

    float bh  = b1[h];
    float w2h = W2[h];
    float vals[PB];
#pragma unroll
    for (int q = 0; q < PB / 2; q++) {
        union { unsigned long long u; float2 f; } cv;
        cv.u = acc2[q];
        vals[2 * q + 0] = fmaxf(cv.f.x + bh, 0.f) * w2h;
        vals[2 * q + 1] = fmaxf(cv.f.y + bh, 0.f) * w2h;
    }

#pragma unroll
    for (int p = 0; p < PB; p++) {
#pragma unroll
        for (int off = 16; off > 0; off >>= 1)
            vals[p] += __shfl_down_sync(0xFFFFFFFFu, vals[p], off);
    }
    int warp = threadIdx.x >> 5;
    int lane = threadIdx.x & 31;
    if (lane == 0) {
#pragma unroll
        for (int p = 0; p < PB; p++) s_red[warp][p] = vals[p];
    }
    __syncthreads();

    if (threadIdx.x < PB) {
        float s = 0.f;
#pragma unroll
        for (int w = 0; w < 16; w++) s += s_red[w][threadIdx.x];
        out[b0 + threadIdx.x] = s + b2[0];
    }
}

// ---------------------------------------------------------------------------
// launch
// ---------------------------------------------------------------------------
extern "C" void kernel_launch(void* const* d_in, const int* in_sizes, int n_in,
                              void* d_out, int out_size) {
    const float* x   = (const float*)d_in[0];
    const void*  ei  = d_in[1];
    const void*  tar = d_in[2];
    const float* W1  = (const float*)d_in[3];
    const float* b1  = (const float*)d_in[4];
    const float* W2  = (const float*)d_in[5];
    const float* b2  = (const float*)d_in[6];
    float*       out = (float*)d_out;

    (void)in_sizes; (void)n_in; (void)out_size;

    detect_kernel<<<1, 32>>>((const unsigned int*)ei);
    scatter_kernel<<<(N_EDGES + 255) / 256, 256>>>(ei);
    pairs_kernel<<<N_PAIRS, 128>>>(tar, x);
    mlp_kernel<<<N_PAIRS / PB, HIDDEN>>>(W1, b1, W2, b2, out);
    clear_kernel<<<(N_EDGES + 255) / 256, 256>>>(ei);
}

// round 4
// speedup vs baseline: 1.4289x; 1.1633x over previous
#include <cuda_runtime.h>
#include <stdint.h>

#define N_NODES 10000
#define N_EDGES 320000
#define N_PAIRS 2048
#define IN_CH   128
#define HIDDEN  512

// 4-bit counts, row stride 5120 bytes (1280 u32 words, 16B aligned, covers
// 10240 nibble columns >= 10000). Total 51.2 MB -> fully L2 resident.
#define ROW_W   1280
#define ROW_U4  320              // uint4 chunks per row (32 nibbles each)

__device__ __align__(16) unsigned int g_A[(size_t)N_NODES * ROW_W];
// xs features: [N_PAIRS][2*IN_CH]  (first 128 = x_i*x_j, next 128 = cn_emb)
__device__ __align__(16) float g_XS[N_PAIRS * 2 * IN_CH];
__device__ int g_is64;

// ---------------------------------------------------------------------------
// 0) Detect index dtype: int64 values < 2^32 have all-zero odd 32-bit words.
// ---------------------------------------------------------------------------
__global__ void detect_kernel(const unsigned int* __restrict__ ei32) {
    bool all0 = true;
    for (int j = threadIdx.x; j < 256; j += 32)
        if (ei32[2 * j + 1] != 0u) all0 = false;
    unsigned m = __ballot_sync(0xFFFFFFFFu, all0);
    if (threadIdx.x == 0) g_is64 = (m == 0xFFFFFFFFu) ? 1 : 0;
}

__device__ __forceinline__ long long load_idx(const void* p, long long j) {
    if (g_is64) return ((const long long*)p)[j];
    return (long long)((const int*)p)[j];
}

// ---------------------------------------------------------------------------
// 1) Scatter: nibble(A[s][d]) += 1, nibble(A[d][s]) += 1 (L2-resident atomics)
// ---------------------------------------------------------------------------
__global__ void scatter_kernel(const void* __restrict__ ei) {
    int e = blockIdx.x * blockDim.x + threadIdx.x;
    if (e >= N_EDGES) return;
    long long s = load_idx(ei, e);
    long long d = load_idx(ei, (long long)N_EDGES + e);
    size_t w1 = (size_t)s * ROW_W + (size_t)(d >> 3);
    size_t w2 = (size_t)d * ROW_W + (size_t)(s >> 3);
    atomicAdd(&g_A[w1], 1u << ((d & 7) * 4));
    atomicAdd(&g_A[w2], 1u << ((s & 7) * 4));
}

// ---------------------------------------------------------------------------
// Clear only the touched nibbles (restores zeros for next graph replay)
// ---------------------------------------------------------------------------
__global__ void clear_kernel(const void* __restrict__ ei) {
    int e = blockIdx.x * blockDim.x + threadIdx.x;
    if (e >= N_EDGES) return;
    long long s = load_idx(ei, e);
    long long d = load_idx(ei, (long long)N_EDGES + e);
    size_t w1 = (size_t)s * ROW_W + (size_t)(d >> 3);
    size_t w2 = (size_t)d * ROW_W + (size_t)(s >> 3);
    atomicAnd(&g_A[w1], ~(0xFu << ((d & 7) * 4)));
    atomicAnd(&g_A[w2], ~(0xFu << ((s & 7) * 4)));
}

// ---------------------------------------------------------------------------
// 2) Per-pair: intersect nibble rows A[ti], A[tj]; build xs[b]
// ---------------------------------------------------------------------------
__device__ __forceinline__ unsigned nzmask(unsigned v) {
    return (v | (v >> 1) | (v >> 2) | (v >> 3)) & 0x11111111u;
}

__global__ void pairs_kernel(const void* __restrict__ tar,
                             const float* __restrict__ x) {
    __shared__ int   s_n[512];
    __shared__ float s_w[512];
    __shared__ int   s_cnt;

    int b   = blockIdx.x;
    int tid = threadIdx.x;   // 0..127
    if (tid == 0) s_cnt = 0;
    __syncthreads();

    long long ti = load_idx(tar, b);
    long long tj = load_idx(tar, (long long)N_PAIRS + b);

    const uint4* rowi = reinterpret_cast<const uint4*>(&g_A[(size_t)ti * ROW_W]);
    const uint4* rowj = reinterpret_cast<const uint4*>(&g_A[(size_t)tj * ROW_W]);

    for (int c = tid; c < ROW_U4; c += 128) {
        uint4 a = rowi[c];
        uint4 q = rowj[c];
        unsigned int aw[4] = {a.x, a.y, a.z, a.w};
        unsigned int bw[4] = {q.x, q.y, q.z, q.w};
#pragma unroll
        for (int w = 0; w < 4; w++) {
            unsigned int av = aw[w], bv = bw[w];
            unsigned int m = nzmask(av) & nzmask(bv);
            while (m) {
                int bit = __ffs(m) - 1;           // 4*nibble
                unsigned ua = (av >> bit) & 0xFu;
                unsigned ub = (bv >> bit) & 0xFu;
                int idx = atomicAdd(&s_cnt, 1);
                if (idx < 512) {
                    s_n[idx] = c * 32 + w * 8 + (bit >> 2);
                    s_w[idx] = (float)(ua * ub);
                }
                m &= m - 1;
            }
        }
    }
    __syncthreads();

    int cnt = s_cnt < 512 ? s_cnt : 512;

    float xi = x[(size_t)ti * IN_CH + tid];
    float xj = x[(size_t)tj * IN_CH + tid];

    float acc = 0.f;
    for (int e = 0; e < cnt; e++)
        acc = fmaf(s_w[e], x[(size_t)s_n[e] * IN_CH + tid], acc);

    g_XS[(size_t)b * (2 * IN_CH) + tid]         = xi * xj;
    g_XS[(size_t)b * (2 * IN_CH) + IN_CH + tid] = acc;
}

// ---------------------------------------------------------------------------
// 3) out init: out[b] = b2[0]  (d_out is poisoned before timing)
// ---------------------------------------------------------------------------
__global__ void out_init_kernel(const float* __restrict__ b2, float* __restrict__ out) {
    int i = blockIdx.x * blockDim.x + threadIdx.x;
    if (i < N_PAIRS) out[i] = b2[0];
}

// ---------------------------------------------------------------------------
// 4) Register-tiled fused GEMM:
//    C = XS[2048x256] * W1[256x512]; out[b] += sum_h relu(C+b1)*W2
//    BM=128 pairs x BN=64 hidden x BK=32 per block, 256 threads,
//    thread tile 8p x 4h via packed f32x2 FMA. Grid = 16 x 8 = 128 blocks.
// ---------------------------------------------------------------------------
#define BM 128
#define BN 64
#define BK 32
#define KTOT (2 * IN_CH)
#define NTILES (KTOT / BK)   // 8

__device__ __forceinline__ unsigned long long fma2(
    unsigned long long a, unsigned long long b, unsigned long long c) {
    unsigned long long d;
    asm("fma.rn.f32x2 %0, %1, %2, %3;" : "=l"(d) : "l"(a), "l"(b), "l"(c));
    return d;
}
__device__ __forceinline__ unsigned long long dup2(float w) {
    unsigned long long r;
    asm("mov.b64 %0, {%1, %1};" : "=l"(r) : "r"(__float_as_uint(w)));
    return r;
}

__global__ __launch_bounds__(256, 1)
void mlp_kernel(const float* __restrict__ W1, const float* __restrict__ b1,
                const float* __restrict__ W2, const float* __restrict__ b2,
                float* __restrict__ out) {
    __shared__ __align__(16) float s_x[BK][BM + 4];   // transposed xs tile, 16.9 KB
    __shared__ __align__(16) float s_w[BK][BN];       // 8 KB
    __shared__ float s_red[BM][17];                   // 8.7 KB

    int tid = threadIdx.x;
    int tx  = tid & 15;        // hidden-dim thread coord (0..15)
    int ty  = tid >> 4;        // pair-dim thread coord   (0..15)
    int b0  = (blockIdx.x & 15) * BM;
    int h0  = (blockIdx.x >> 4) * BN;

    // prefetch registers for tile 0
    float4 xr[4];
    float4 wr[2];
#pragma unroll
    for (int l = 0; l < 4; l++) {
        int fi = tid + l * 256;          // float4 index in 128x32 tile
        int p  = fi >> 3;                // row (pair)
        int kc = fi & 7;                 // k-chunk of 4
        xr[l] = *reinterpret_cast<const float4*>(&g_XS[(size_t)(b0 + p) * KTOT + kc * 4]);
    }
#pragma unroll
    for (int l = 0; l < 2; l++) {
        int fi = tid + l * 256;          // float4 index in 32x64 tile
        int kk = fi >> 4;
        int cc = (fi & 15) * 4;
        wr[l] = *reinterpret_cast<const float4*>(&W1[(size_t)kk * HIDDEN + h0 + cc]);
    }

    unsigned long long acc2[4][4];
#pragma unroll
    for (int i = 0; i < 4; i++)
#pragma unroll
        for (int j = 0; j < 4; j++) acc2[i][j] = 0ull;

    for (int t = 0; t < NTILES; t++) {
        // store prefetched tile to smem
#pragma unroll
        for (int l = 0; l < 4; l++) {
            int fi = tid + l * 256;
            int p  = fi >> 3;
            int kc = fi & 7;
            s_x[kc * 4 + 0][p] = xr[l].x;
            s_x[kc * 4 + 1][p] = xr[l].y;
            s_x[kc * 4 + 2][p] = xr[l].z;
            s_x[kc * 4 + 3][p] = xr[l].w;
        }
#pragma unroll
        for (int l = 0; l < 2; l++) {
            int fi = tid + l * 256;
            int kk = fi >> 4;
            int cc = (fi & 15) * 4;
            *reinterpret_cast<float4*>(&s_w[kk][cc]) = wr[l];
        }
        __syncthreads();

        // prefetch next tile while computing
        if (t + 1 < NTILES) {
            int k0 = (t + 1) * BK;
#pragma unroll
            for (int l = 0; l < 4; l++) {
                int fi = tid + l * 256;
                int p  = fi >> 3;
                int kc = fi & 7;
                xr[l] = *reinterpret_cast<const float4*>(
                    &g_XS[(size_t)(b0 + p) * KTOT + k0 + kc * 4]);
            }
#pragma unroll
            for (int l = 0; l < 2; l++) {
                int fi = tid + l * 256;
                int kk = fi >> 4;
                int cc = (fi & 15) * 4;
                wr[l] = *reinterpret_cast<const float4*>(
                    &W1[(size_t)(k0 + kk) * HIDDEN + h0 + cc]);
            }
        }

#pragma unroll 8
        for (int k = 0; k < BK; k++) {
            float4 wv = *reinterpret_cast<const float4*>(&s_w[k][tx * 4]);
            unsigned long long wd[4];
            wd[0] = dup2(wv.x); wd[1] = dup2(wv.y);
            wd[2] = dup2(wv.z); wd[3] = dup2(wv.w);
            ulonglong2 xa = *reinterpret_cast<const ulonglong2*>(&s_x[k][ty * 8]);
            ulonglong2 xb = *reinterpret_cast<const ulonglong2*>(&s_x[k][ty * 8 + 4]);
            unsigned long long xp[4] = {xa.x, xa.y, xb.x, xb.y};
#pragma unroll
            for (int pp = 0; pp < 4; pp++)
#pragma unroll
                for (int hh = 0; hh < 4; hh++)
                    acc2[pp][hh] = fma2(xp[pp], wd[hh], acc2[pp][hh]);
        }
        __syncthreads();
    }

    // epilogue: relu + W2 weighting, reduce over this block's 64 h
    float4 b1v = *reinterpret_cast<const float4*>(&b1[h0 + tx * 4]);
    float4 w2v = *reinterpret_cast<const float4*>(&W2[h0 + tx * 4]);
    float bb[4] = {b1v.x, b1v.y, b1v.z, b1v.w};
    float ww[4] = {w2v.x, w2v.y, w2v.z, w2v.w};

    float pval[8];
#pragma unroll
    for (int pp = 0; pp < 4; pp++) {
        float lo = 0.f, hi = 0.f;
#pragma unroll
        for (int hh = 0; hh < 4; hh++) {
            union { unsigned long long u; float2 f; } cv;
            cv.u = acc2[pp][hh];
            lo += fmaxf(cv.f.x + bb[hh], 0.f) * ww[hh];
            hi += fmaxf(cv.f.y + bb[hh], 0.f) * ww[hh];
        }
        pval[pp * 2 + 0] = lo;
        pval[pp * 2 + 1] = hi;
    }

#pragma unroll
    for (int q = 0; q < 8; q++)
        s_red[ty * 8 + q][tx] = pval[q];
    __syncthreads();

    if (tid < BM) {
        float s = 0.f;
#pragma unroll
        for (int t = 0; t < 16; t++) s += s_red[tid][t];
        atomicAdd(&out[b0 + tid], s);
    }
}

// ---------------------------------------------------------------------------
// launch
// ---------------------------------------------------------------------------
extern "C" void kernel_launch(void* const* d_in, const int* in_sizes, int n_in,
                              void* d_out, int out_size) {
    const float* x   = (const float*)d_in[0];
    const void*  ei  = d_in[1];
    const void*  tar = d_in[2];
    const float* W1  = (const float*)d_in[3];
    const float* b1  = (const float*)d_in[4];
    const float* W2  = (const float*)d_in[5];
    const float* b2  = (const float*)d_in[6];
    float*       out = (float*)d_out;

    (void)in_sizes; (void)n_in; (void)out_size;

    detect_kernel<<<1, 32>>>((const unsigned int*)ei);
    scatter_kernel<<<(N_EDGES + 255) / 256, 256>>>(ei);
    out_init_kernel<<<(N_PAIRS + 255) / 256, 256>>>(b2, out);
    pairs_kernel<<<N_PAIRS, 128>>>(tar, x);
    mlp_kernel<<<128, 256>>>(W1, b1, W2, b2, out);
    clear_kernel<<<(N_EDGES + 255) / 256, 256>>>(ei);
}